// round 2
// baseline (speedup 1.0000x reference)
#include <cuda_runtime.h>
#include <cstdint>
#include <cstddef>

#define SEQ 4096
#define DM  1024
#define NH  16
#define HD  64
#define NKEY 32
#define NNG 4094

// Scratch (device globals: allocation-free)
__device__ float g_q[SEQ * DM];
__device__ float g_k[SEQ * DM];
__device__ float g_v[SEQ * DM];
__device__ float g_attn[SEQ * DM];
__device__ int   g_idx_is64;

// ---------------------------------------------------------------------------
// idx dtype detector: if idx is int64 (values in [0,4096)), the hi 32-bit
// words are all zero. If int32, words 1,3,5,7 are randint(1,S) -> never 0.
// ---------------------------------------------------------------------------
__global__ void detect_idx_kernel(const int* __restrict__ idx32) {
    g_idx_is64 = ((idx32[1] | idx32[3] | idx32[5] | idx32[7]) == 0) ? 1 : 0;
}

// ---------------------------------------------------------------------------
// TF32 helpers
// ---------------------------------------------------------------------------
__device__ __forceinline__ uint32_t f2tf32(float x) {
    uint32_t r;
    asm("cvt.rna.tf32.f32 %0, %1;" : "=r"(r) : "f"(x));
    return r;
}

__device__ __forceinline__ void mma_tf32(float c[4], const uint32_t a[4], const uint32_t b[2]) {
    asm volatile(
        "mma.sync.aligned.m16n8k8.row.col.f32.tf32.tf32.f32 "
        "{%0,%1,%2,%3}, {%4,%5,%6,%7}, {%8,%9}, {%0,%1,%2,%3};"
        : "+f"(c[0]), "+f"(c[1]), "+f"(c[2]), "+f"(c[3])
        : "r"(a[0]), "r"(a[1]), "r"(a[2]), "r"(a[3]),
          "r"(b[0]), "r"(b[1]));
}

// ---------------------------------------------------------------------------
// TF32 GEMM: C[4096,1024] = A[4096,1024] * B[1024,1024], fp32 in/out.
// 128x128 block tile, BK=16, 8 warps (4x2), warp tile 32x64, m16n8k8 MMA.
// Double-buffered shared memory; padded strides for conflict-free frag loads.
// ---------------------------------------------------------------------------
#define BM 128
#define BN 128
#define BK 16
#define PA 20    // As row stride (floats)
#define PB 136   // Bs row stride (floats)

__global__ __launch_bounds__(256, 1)
void gemm_tf32_kernel(const float* __restrict__ A, const float* __restrict__ B,
                      float* __restrict__ C) {
    const int N = 1024, K = 1024;
    __shared__ float As[2][BM * PA];
    __shared__ float Bs[2][BK * PB];

    const int bm = blockIdx.y * BM;
    const int bn = blockIdx.x * BN;
    const int t = threadIdx.x;
    const int lane = t & 31;
    const int warp = t >> 5;
    const int wr = warp >> 1;    // 0..3  (32-row slabs)
    const int wc = warp & 1;     // 0..1  (64-col slabs)

    float acc[2][8][4];
#pragma unroll
    for (int mi = 0; mi < 2; mi++)
#pragma unroll
        for (int ni = 0; ni < 8; ni++)
#pragma unroll
            for (int e = 0; e < 4; e++) acc[mi][ni][e] = 0.f;

    // ---- prologue: load k-tile 0 into buffer 0 ----
    {
        const int k0 = 0;
#pragma unroll
        for (int i = 0; i < 2; i++) {
            int f  = t + i * 256;          // 0..511 float4 of A tile
            int r  = f >> 2;
            int kc = (f & 3) << 2;
            float4 v4 = *(const float4*)(A + (size_t)(bm + r) * K + k0 + kc);
            uint32_t* d = (uint32_t*)&As[0][r * PA + kc];
            d[0] = f2tf32(v4.x); d[1] = f2tf32(v4.y);
            d[2] = f2tf32(v4.z); d[3] = f2tf32(v4.w);

            int kr = f >> 5;               // 0..15
            int cc = (f & 31) << 2;
            float4 w4 = *(const float4*)(B + (size_t)(k0 + kr) * N + bn + cc);
            uint32_t* db = (uint32_t*)&Bs[0][kr * PB + cc];
            db[0] = f2tf32(w4.x); db[1] = f2tf32(w4.y);
            db[2] = f2tf32(w4.z); db[3] = f2tf32(w4.w);
        }
    }
    __syncthreads();

    const int NT = K / BK;   // 64
    for (int kt = 0; kt < NT; kt++) {
        const int cur = kt & 1;

        // ---- prefetch next tile (global -> regs) ----
        float4 pa[2], pb[2];
        if (kt < NT - 1) {
            const int k0 = (kt + 1) * BK;
#pragma unroll
            for (int i = 0; i < 2; i++) {
                int f  = t + i * 256;
                int r  = f >> 2;
                int kc = (f & 3) << 2;
                pa[i] = *(const float4*)(A + (size_t)(bm + r) * K + k0 + kc);
                int kr = f >> 5;
                int cc = (f & 31) << 2;
                pb[i] = *(const float4*)(B + (size_t)(k0 + kr) * N + bn + cc);
            }
        }

        // ---- compute on current buffer ----
        const uint32_t* as = (const uint32_t*)&As[cur][0];
        const uint32_t* bs = (const uint32_t*)&Bs[cur][0];
#pragma unroll
        for (int kk = 0; kk < BK; kk += 8) {
            uint32_t af[2][4];
            const int r0 = wr * 32 + (lane >> 2);
            const int ac = kk + (lane & 3);
#pragma unroll
            for (int mi = 0; mi < 2; mi++) {
                int r = r0 + mi * 16;
                af[mi][0] = as[r * PA + ac];
                af[mi][1] = as[(r + 8) * PA + ac];
                af[mi][2] = as[r * PA + ac + 4];
                af[mi][3] = as[(r + 8) * PA + ac + 4];
            }
            uint32_t bf[8][2];
            const int kr = kk + (lane & 3);
            const int c0 = wc * 64 + (lane >> 2);
#pragma unroll
            for (int ni = 0; ni < 8; ni++) {
                int c = c0 + ni * 8;
                bf[ni][0] = bs[kr * PB + c];
                bf[ni][1] = bs[(kr + 4) * PB + c];
            }
#pragma unroll
            for (int mi = 0; mi < 2; mi++)
#pragma unroll
                for (int ni = 0; ni < 8; ni++)
                    mma_tf32(acc[mi][ni], af[mi], bf[ni]);
        }

        // ---- store prefetched tile into other buffer ----
        if (kt < NT - 1) {
            const int nxt = cur ^ 1;
#pragma unroll
            for (int i = 0; i < 2; i++) {
                int f  = t + i * 256;
                int r  = f >> 2;
                int kc = (f & 3) << 2;
                uint32_t* d = (uint32_t*)&As[nxt][r * PA + kc];
                d[0] = f2tf32(pa[i].x); d[1] = f2tf32(pa[i].y);
                d[2] = f2tf32(pa[i].z); d[3] = f2tf32(pa[i].w);
                int kr = f >> 5;
                int cc = (f & 31) << 2;
                uint32_t* db = (uint32_t*)&Bs[nxt][kr * PB + cc];
                db[0] = f2tf32(pb[i].x); db[1] = f2tf32(pb[i].y);
                db[2] = f2tf32(pb[i].z); db[3] = f2tf32(pb[i].w);
            }
            __syncthreads();
        }
    }

    // ---- epilogue ----
#pragma unroll
    for (int mi = 0; mi < 2; mi++) {
#pragma unroll
        for (int ni = 0; ni < 8; ni++) {
            int r = bm + wr * 32 + mi * 16 + (lane >> 2);
            int c = bn + wc * 64 + ni * 8 + ((lane & 3) << 1);
            float2 v0 = make_float2(acc[mi][ni][0], acc[mi][ni][1]);
            float2 v1 = make_float2(acc[mi][ni][2], acc[mi][ni][3]);
            *(float2*)(C + (size_t)r * N + c) = v0;
            *(float2*)(C + (size_t)(r + 8) * N + c) = v1;
        }
    }
}

// ---------------------------------------------------------------------------
// Sparse attention: one block per non-global query position (p = n+1),
// 512 threads = 16 warps = 16 heads. Lane j handles selected key j.
// ---------------------------------------------------------------------------
__global__ __launch_bounds__(512)
void sparse_attn_kernel(const float* __restrict__ qb, const float* __restrict__ kb,
                        const float* __restrict__ vb, const void* __restrict__ idxp,
                        float* __restrict__ ob) {
    __shared__ float qs[DM];
    const int n = blockIdx.x;
    const int p = n + 1;
    const int t = threadIdx.x;

    if (t < DM / 4)
        ((float4*)qs)[t] = ((const float4*)(qb + (size_t)p * DM))[t];
    __syncthreads();

    const int h = t >> 5;
    const int lane = t & 31;

    int row;
    if (g_idx_is64) {
        row = (int)((const long long*)idxp)[(size_t)n * NKEY + lane];
    } else {
        row = ((const int*)idxp)[(size_t)n * NKEY + lane];
    }

    const float* kr = kb + (size_t)row * DM + h * HD;
    const float* qh = qs + h * HD;

    float a = 0.f;
#pragma unroll
    for (int c = 0; c < 16; c++) {
        float4 kv = ((const float4*)kr)[c];
        float4 qv = ((const float4*)qh)[c];
        a += kv.x * qv.x + kv.y * qv.y + kv.z * qv.z + kv.w * qv.w;
    }
    float logit = a * 0.125f;

    // warp softmax over the 32 keys
    float m = logit;
#pragma unroll
    for (int o = 16; o > 0; o >>= 1) m = fmaxf(m, __shfl_xor_sync(0xFFFFFFFFu, m, o));
    float e = __expf(logit - m);
    float s = e;
#pragma unroll
    for (int o = 16; o > 0; o >>= 1) s += __shfl_xor_sync(0xFFFFFFFFu, s, o);
    const float prob = e / s;

    // P * V: remap lanes to dims, broadcast (p_j, row_j) from lane j
    float o0 = 0.f, o1 = 0.f;
#pragma unroll
    for (int j = 0; j < NKEY; j++) {
        float pj = __shfl_sync(0xFFFFFFFFu, prob, j);
        int   rj = __shfl_sync(0xFFFFFFFFu, row, j);
        const float* vr = vb + (size_t)rj * DM + h * HD;
        o0 += pj * vr[lane];
        o1 += pj * vr[32 + lane];
    }
    ob[(size_t)p * DM + h * HD + lane] = o0;
    ob[(size_t)p * DM + h * HD + 32 + lane] = o1;
}

// ---------------------------------------------------------------------------
// Global attention: positions {0, S-1}, full softmax over all S keys.
// One block per (position, head); 256 threads; smem logits.
// ---------------------------------------------------------------------------
__global__ __launch_bounds__(256)
void global_attn_kernel(const float* __restrict__ qb, const float* __restrict__ kb,
                        const float* __restrict__ vb, float* __restrict__ ob) {
    __shared__ float lg[SEQ];     // 16 KB
    __shared__ float qsh[HD];
    __shared__ float red[256];

    const int h = blockIdx.x & (NH - 1);
    const int p = (blockIdx.x >> 4) ? (SEQ - 1) : 0;
    const int t = threadIdx.x;

    if (t < HD / 4)
        ((float4*)qsh)[t] = *(const float4*)(qb + (size_t)p * DM + h * HD + t * 4);
    __syncthreads();

    float lmax = -1e30f;
    for (int j = t; j < SEQ; j += 256) {
        const float* kr = kb + (size_t)j * DM + h * HD;
        float a = 0.f;
#pragma unroll
        for (int c = 0; c < 16; c++) {
            float4 kv = ((const float4*)kr)[c];
            float4 qv = ((const float4*)qsh)[c];
            a += kv.x * qv.x + kv.y * qv.y + kv.z * qv.z + kv.w * qv.w;
        }
        a *= 0.125f;
        lg[j] = a;
        lmax = fmaxf(lmax, a);
    }
    red[t] = lmax; __syncthreads();
    for (int o = 128; o > 0; o >>= 1) {
        if (t < o) red[t] = fmaxf(red[t], red[t + o]);
        __syncthreads();
    }
    const float Mx = red[0];
    __syncthreads();

    float ss = 0.f;
    for (int j = t; j < SEQ; j += 256) {
        float e = __expf(lg[j] - Mx);
        lg[j] = e;
        ss += e;
    }
    red[t] = ss; __syncthreads();
    for (int o = 128; o > 0; o >>= 1) {
        if (t < o) red[t] += red[t + o];
        __syncthreads();
    }
    const float inv = 1.f / red[0];
    __syncthreads();

    const int d = t & (HD - 1);
    const int part = t >> 6;     // 0..3
    float o = 0.f;
    for (int j = part; j < SEQ; j += 4)
        o += lg[j] * vb[(size_t)j * DM + h * HD + d];
    red[t] = o; __syncthreads();
    if (t < HD) {
        float r = (red[t] + red[t + 64] + red[t + 128] + red[t + 192]) * inv;
        ob[(size_t)p * DM + h * HD + t] = r;
    }
}

// ---------------------------------------------------------------------------
// Launch
// ---------------------------------------------------------------------------
extern "C" void kernel_launch(void* const* d_in, const int* in_sizes, int n_in,
                              void* d_out, int out_size) {
    const float* Q  = (const float*)d_in[0];
    const float* K  = (const float*)d_in[1];
    const float* V  = (const float*)d_in[2];
    const float* Wq = (const float*)d_in[3];
    const float* Wk = (const float*)d_in[4];
    const float* Wv = (const float*)d_in[5];
    const float* Wo = (const float*)d_in[6];
    const void*  idx = d_in[7];
    float* out = (float*)d_out;

    float *q, *k, *v, *attn;
    cudaGetSymbolAddress((void**)&q,    g_q);
    cudaGetSymbolAddress((void**)&k,    g_k);
    cudaGetSymbolAddress((void**)&v,    g_v);
    cudaGetSymbolAddress((void**)&attn, g_attn);

    detect_idx_kernel<<<1, 1>>>((const int*)idx);

    dim3 gg(DM / BN, SEQ / BM);   // (8, 32)
    gemm_tf32_kernel<<<gg, 256>>>(Q, Wq, q);
    gemm_tf32_kernel<<<gg, 256>>>(K, Wk, k);
    gemm_tf32_kernel<<<gg, 256>>>(V, Wv, v);

    sparse_attn_kernel<<<NNG, 512>>>(q, k, v, idx, attn);
    global_attn_kernel<<<2 * NH, 256>>>(q, k, v, attn);

    gemm_tf32_kernel<<<gg, 256>>>(attn, Wo, out);
}